// round 13
// baseline (speedup 1.0000x reference)
#include <cuda_runtime.h>
#include <cuda_fp16.h>
#include <cstdint>

#define P_PERM  200000
#define N_NODES 100000
#define PT      128
#define NTILES  ((P_PERM + PT - 1) / PT)
#define FULLM   0xffffffffu

#define SWZ(o) ((o) ^ (((o) >> 3) & 0x70))

// named barrier ids (0 = __syncthreads)
#define BAR_FREE0 1
#define BAR_FREE1 2
#define BAR_FULL0 3
#define BAR_FULL1 4
#define BAR_SYNC(id)   asm volatile("bar.sync %0, 256;"   :: "r"(id) : "memory")
#define BAR_ARRIVE(id) asm volatile("bar.arrive %0, 256;" :: "r"(id) : "memory")

// B operands pre-packed in fp16 mma fragment layout.
__device__ __align__(16) uint4 g_W1f[16 * 4 * 4 * 32];  // einsum weights, 128KB
__device__ __align__(16) uint4 g_W2f[4 * 4 * 32];       // w_lin, 8KB
__device__ __align__(16) uint4 g_W3f[2 * 4 * 4 * 32];   // w_deg1 (2 k-chunks), 16KB
// nfeat converted to fp16: row-major, 8 uint4 per row (64 fp16 = 128B)
__device__ __align__(16) uint4 g_nfh[(size_t)N_NODES * 8];   // 12.8MB

// ---------------------------- SMEM layout (bytes) ---------------------------
#define XB0   0        // four 16KB fp16 X tiles (128x64)
#define XB1   16384
#define XB2   32768
#define XB3   49152
#define SBOND 65536    // 512B: bond_emb fp16, uint4[32]
#define SDS   66048    // 512 f
#define SWD0  68096    // 512 f
#define SBD0  70144    // 128 f
#define SBIA  70656    // 64 f
#define SBLI  70912    // 64 f
#define SBD1  71168    // 64 f
#define SPV   71424    // 128 f
#define SPR   71936    // 128 i
#define SMEM_BYTES 72448

// ------------------------------ asm helpers --------------------------------
__device__ __forceinline__ void ldm_x4(uint32_t* r, uint32_t a) {
    asm volatile("ldmatrix.sync.aligned.m8n8.x4.shared.b16 {%0,%1,%2,%3}, [%4];"
                 : "=r"(r[0]), "=r"(r[1]), "=r"(r[2]), "=r"(r[3]) : "r"(a));
}
__device__ __forceinline__ void mma16816(float* d, const uint32_t* a, uint32_t b0, uint32_t b1) {
    asm volatile(
        "mma.sync.aligned.m16n8k16.row.col.f32.f16.f16.f32 "
        "{%0,%1,%2,%3}, {%4,%5,%6,%7}, {%8,%9}, {%0,%1,%2,%3};"
        : "+f"(d[0]), "+f"(d[1]), "+f"(d[2]), "+f"(d[3])
        : "r"(a[0]), "r"(a[1]), "r"(a[2]), "r"(a[3]), "r"(b0), "r"(b1));
}
__device__ __forceinline__ uint32_t s2u(const void* p) {
    uint32_t a;
    asm("{ .reg .u64 t; cvta.to.shared.u64 t, %1; cvt.u32.u64 %0, t; }" : "=r"(a) : "l"(p));
    return a;
}
__device__ __forceinline__ uint32_t pack_h2(float a, float b) {
    __half2 h = __floats2half2_rn(a, b);
    return *(uint32_t*)&h;
}

// ---- m32 x n(16*NFP) warp GEMM over K=64, single fp16 term ------------------
template<int NFP>
__device__ __forceinline__ void gemm_tile(float (&acc)[2][2 * NFP][4], uint32_t xh,
                                          const uint4* __restrict__ wf, int nfp0,
                                          int rbase, int lane) {
    const int sub = lane >> 3, rin = lane & 7;
    const uint32_t aRow = (uint32_t)(rbase + ((sub & 1) << 3) + rin) * 128;
    const uint32_t aCol = (uint32_t)((sub >> 1) << 4);
    #pragma unroll
    for (int kc = 0; kc < 4; kc++) {
        uint32_t aoff = SWZ(aRow + aCol + kc * 32);
        uint32_t ah0[4], ah1[4];
        ldm_x4(ah0, xh + aoff);
        ldm_x4(ah1, xh + aoff + 2048);   // +16 rows
        uint4 bfr[NFP];
        #pragma unroll
        for (int pg = 0; pg < NFP; pg++)
            bfr[pg] = wf[(kc * 4 + nfp0 + pg) * 32 + lane];
        #pragma unroll
        for (int pg = 0; pg < NFP; pg++) {
            mma16816(acc[0][2 * pg + 0], ah0, bfr[pg].x, bfr[pg].y);
            mma16816(acc[1][2 * pg + 0], ah1, bfr[pg].x, bfr[pg].y);
            mma16816(acc[0][2 * pg + 1], ah0, bfr[pg].z, bfr[pg].w);
            mma16816(acc[1][2 * pg + 1], ah1, bfr[pg].z, bfr[pg].w);
        }
    }
}

// ============================================================================
// prep: build fp16 B-fragment tables + fp16 nfeat table
// ============================================================================
__global__ void prep_kernel(const float* __restrict__ weights,
                            const float* __restrict__ w_lin,
                            const float* __restrict__ w_deg1,
                            const float* __restrict__ nfeat) {
    int idx = blockIdx.x * 256 + threadIdx.x;
    if (idx < 8192) {
        const int lane = idx & 31;
        const int nfp  = (idx >> 5) & 3;
        const int kc   = (idx >> 7) & 3;
        const int ce = nfp * 16 + (lane >> 2);
        const int co = ce + 8;
        const int kb = kc * 16 + (lane & 3) * 2;
        {
            int a = idx >> 9;
            uint4 v;
            v.x = pack_h2(weights[(((kb + 0) << 6) + ce) * 16 + a],
                          weights[(((kb + 1) << 6) + ce) * 16 + a]);
            v.y = pack_h2(weights[(((kb + 8) << 6) + ce) * 16 + a],
                          weights[(((kb + 9) << 6) + ce) * 16 + a]);
            v.z = pack_h2(weights[(((kb + 0) << 6) + co) * 16 + a],
                          weights[(((kb + 1) << 6) + co) * 16 + a]);
            v.w = pack_h2(weights[(((kb + 8) << 6) + co) * 16 + a],
                          weights[(((kb + 9) << 6) + co) * 16 + a]);
            g_W1f[idx] = v;
        }
        if (idx < 512) {
            const float* se = w_lin + ce * 64;
            const float* so = w_lin + co * 64;
            uint4 v;
            v.x = pack_h2(se[kb], se[kb + 1]);
            v.y = pack_h2(se[kb + 8], se[kb + 9]);
            v.z = pack_h2(so[kb], so[kb + 1]);
            v.w = pack_h2(so[kb + 8], so[kb + 9]);
            g_W2f[idx] = v;
        }
        if (idx < 1024) {
            int ch = idx >> 9;
            const float* se = w_deg1 + ce * 128 + ch * 64;
            const float* so = w_deg1 + co * 128 + ch * 64;
            uint4 v;
            v.x = pack_h2(se[kb], se[kb + 1]);
            v.y = pack_h2(se[kb + 8], se[kb + 9]);
            v.z = pack_h2(so[kb], so[kb + 1]);
            v.w = pack_h2(so[kb + 8], so[kb + 9]);
            g_W3f[idx] = v;
        }
    } else {
        int j = idx - 8192;                 // 0 .. N_NODES*8-1
        if (j < N_NODES * 8) {
            const float4* src = (const float4*)(nfeat) + (size_t)j * 2;
            float4 a = src[0], b = src[1];
            uint4 v;
            v.x = pack_h2(a.x, a.y); v.y = pack_h2(a.z, a.w);
            v.z = pack_h2(b.x, b.y); v.w = pack_h2(b.z, b.w);
            g_nfh[j] = v;
        }
    }
}

// ============================================================================
// fused: warp-specialized, fp16, decoupled named-barrier pipeline (4 buffers)
// producer MIO diet: bond in registers (SEL select), packed 2-shfl metadata
// ============================================================================
__global__ __launch_bounds__(256, 2)
void fused_kernel(const float* __restrict__ degs,
                  const float* __restrict__ n2p_val,
                  const float* __restrict__ e2p_val,
                  const float* __restrict__ pool_val,
                  const float* __restrict__ bias,
                  const float* __restrict__ w_deg0,
                  const float* __restrict__ b_deg0,
                  const float* __restrict__ b_deg1,
                  const float* __restrict__ b_lin,
                  const float* __restrict__ bond_emb,
                  const int*   __restrict__ edge_feat_idx,
                  const int*   __restrict__ n2p_col,
                  const int*   __restrict__ e2p_col,
                  const int*   __restrict__ pool_row,
                  float*       __restrict__ out) {
    extern __shared__ char sm[];
    const uint32_t SB = s2u(sm);
    const int tid = threadIdx.x;
    const int warp = tid >> 5, lane = tid & 31;
    const int p0 = blockIdx.x * PT;

    uint4* s_bondh = (uint4*)(sm + SBOND);
    float* s_ds   = (float*)(sm + SDS);
    float* s_wd0  = (float*)(sm + SWD0);
    float* s_bd0  = (float*)(sm + SBD0);
    float* s_bia  = (float*)(sm + SBIA);
    float* s_bli  = (float*)(sm + SBLI);
    float* s_bd1  = (float*)(sm + SBD1);
    float* s_pv   = (float*)(sm + SPV);
    int*   s_pr   = (int*)(sm + SPR);

    if (tid < 32) {   // bond_emb -> fp16, 4 rows x 8 uint4
        int row = tid >> 3, c8 = tid & 7;
        const float* s = bond_emb + row * 64 + c8 * 8;
        uint4 v;
        v.x = pack_h2(s[0], s[1]); v.y = pack_h2(s[2], s[3]);
        v.z = pack_h2(s[4], s[5]); v.w = pack_h2(s[6], s[7]);
        s_bondh[tid] = v;
    }
    for (int i = tid; i < 512; i += 256) s_wd0[i] = w_deg0[i];
    if (tid < 128) s_bd0[tid] = b_deg0[tid];
    if (tid < 64) { s_bia[tid] = bias[tid]; s_bli[tid] = b_lin[tid]; s_bd1[tid] = b_deg1[tid]; }
    __syncthreads();

    const int rbase = (warp & 3) * 32;

    float acc1[2][8][4];
    #pragma unroll
    for (int m = 0; m < 2; m++)
        #pragma unroll
        for (int n = 0; n < 8; n++)
            #pragma unroll
            for (int j = 0; j < 4; j++) acc1[m][n][j] = 0.f;

    const int p = tid - 128;                 // producer row id (warp>=4)
    const bool valid = (p0 + p) < P_PERM;
    const int pc = valid ? (p0 + p) : (P_PERM - 1);

    // producer-only: bond rows in registers (this lane's col-group of each row)
    uint4 rb0, rb1, rb2, rb3;
    if (warp >= 4) {
        rb0 = s_bondh[0 * 8 + (lane & 7)];
        rb1 = s_bondh[1 * 8 + (lane & 7)];
        rb2 = s_bondh[2 * 8 + (lane & 7)];
        rb3 = s_bondh[3 * 8 + (lane & 7)];
    }

    uint32_t mnb[4];   // nc | bj<<27
    uint32_t mv[4];    // fp16(vn) | fp16(ve)<<16
    float vns_f[4];    // fp32 vn (for ds only)
    int ncs_i[4];

    // ======== mainloop: 8 epochs x 2 slices, decoupled named barriers ========
    #pragma unroll
    for (int e = 0; e < 8; e++) {
        if (warp >= 4) {
            const int b = e & 1;
            if (b == 0) {                    // load 4-slice index group + prefetch bj
                int g = e >> 1;
                int4 nc4 = ((const int4*)n2p_col)[pc * 4 + g];
                int4 ec4 = ((const int4*)e2p_col)[pc * 4 + g];
                float4 vn4 = ((const float4*)n2p_val)[pc * 4 + g];
                float4 ve4 = ((const float4*)e2p_val)[pc * 4 + g];
                int bj0 = edge_feat_idx[ec4.x];
                int bj1 = edge_feat_idx[ec4.y];
                int bj2 = edge_feat_idx[ec4.z];
                int bj3 = edge_feat_idx[ec4.w];
                float v0 = valid ? vn4.x : 0.f, v1 = valid ? vn4.y : 0.f;
                float v2 = valid ? vn4.z : 0.f, v3 = valid ? vn4.w : 0.f;
                float w0 = valid ? ve4.x : 0.f, w1 = valid ? ve4.y : 0.f;
                float w2 = valid ? ve4.z : 0.f, w3 = valid ? ve4.w : 0.f;
                mnb[0] = (uint32_t)nc4.x | ((uint32_t)bj0 << 27);
                mnb[1] = (uint32_t)nc4.y | ((uint32_t)bj1 << 27);
                mnb[2] = (uint32_t)nc4.z | ((uint32_t)bj2 << 27);
                mnb[3] = (uint32_t)nc4.w | ((uint32_t)bj3 << 27);
                mv[0] = pack_h2(v0, w0); mv[1] = pack_h2(v1, w1);
                mv[2] = pack_h2(v2, w2); mv[3] = pack_h2(v3, w3);
                vns_f[0] = v0; vns_f[1] = v1; vns_f[2] = v2; vns_f[3] = v3;
                ncs_i[0] = nc4.x; ncs_i[1] = nc4.y; ncs_i[2] = nc4.z; ncs_i[3] = nc4.w;
            }
            if (e >= 2) BAR_SYNC(BAR_FREE0 + b);   // wait pair free
            #pragma unroll
            for (int s = 0; s < 2; s++) {
                const int a = 2 * e + s;
                const int ai = a & 3;
                if (ai == (a >> 2))                 // slices 0,5,10,15
                    s_ds[p * 4 + (a >> 2)] = vns_f[ai] * degs[ncs_i[ai]];
                uint32_t m_nb = mnb[ai];
                uint32_t m_v  = mv[ai];
                char* xh = sm + (2 * b + s) * 16384;
                const int r0 = (warp - 4) * 32;
                #pragma unroll
                for (int pass = 0; pass < 8; pass++) {
                    int src = pass * 4 + (lane >> 3);
                    uint32_t nb_r = __shfl_sync(FULLM, m_nb, src);
                    uint32_t v_r  = __shfl_sync(FULLM, m_v,  src);
                    uint32_t nc_r = nb_r & 0x07FFFFFFu;
                    uint32_t bj_r = nb_r >> 27;
                    int row = r0 + pass * 4 + (lane >> 3);
                    uint4 nv = g_nfh[(size_t)nc_r * 8 + (lane & 7)];     // 1 LDG.128
                    // bond row via register select (no LDS)
                    uint4 t0 = (bj_r & 2) ? rb2 : rb0;
                    uint4 t1 = (bj_r & 2) ? rb3 : rb1;
                    uint4 bv = (bj_r & 1) ? t1 : t0;
                    __half2 vv = *(__half2*)&v_r;
                    __half2 vn2 = __half2half2(__low2half(vv));
                    __half2 ve2 = __half2half2(__high2half(vv));
                    uint4 v;
                    *(__half2*)&v.x = __hfma2(vn2, *(const __half2*)&nv.x,
                                              __hmul2(ve2, *(const __half2*)&bv.x));
                    *(__half2*)&v.y = __hfma2(vn2, *(const __half2*)&nv.y,
                                              __hmul2(ve2, *(const __half2*)&bv.y));
                    *(__half2*)&v.z = __hfma2(vn2, *(const __half2*)&nv.z,
                                              __hmul2(ve2, *(const __half2*)&bv.z));
                    *(__half2*)&v.w = __hfma2(vn2, *(const __half2*)&nv.w,
                                              __hmul2(ve2, *(const __half2*)&bv.w));
                    uint32_t off = SWZ((uint32_t)row * 128 + ((lane & 7) << 4));
                    *(uint4*)(xh + off) = v;
                }
            }
            BAR_ARRIVE(BAR_FULL0 + b);             // pair filled
        } else if (e > 0) {
            const int b = (e - 1) & 1;
            BAR_SYNC(BAR_FULL0 + b);               // wait pair full
            #pragma unroll
            for (int s = 0; s < 2; s++) {
                const int a = 2 * (e - 1) + s;
                gemm_tile<4>(acc1, SB + (2 * b + s) * 16384, g_W1f + a * 512, 0, rbase, lane);
            }
            BAR_ARRIVE(BAR_FREE0 + b);             // pair free
        }
    }

    // ===================== epilogue phase A ==================================
    if (warp < 4) {
        BAR_SYNC(BAR_FULL1);
        gemm_tile<4>(acc1, SB + XB2, g_W1f + 14 * 512, 0, rbase, lane);
        gemm_tile<4>(acc1, SB + XB3, g_W1f + 15 * 512, 0, rbase, lane);
        #pragma unroll
        for (int mt = 0; mt < 2; mt++)
            #pragma unroll
            for (int nf = 0; nf < 8; nf++) {
                int c0 = nf * 8 + (lane & 3) * 2;
                #pragma unroll
                for (int pr2 = 0; pr2 < 2; pr2++) {
                    int row = rbase + mt * 16 + (lane >> 2) + pr2 * 8;
                    float f0 = fmaxf(acc1[mt][nf][pr2 * 2 + 0] + s_bia[c0], 0.f);
                    float f1 = fmaxf(acc1[mt][nf][pr2 * 2 + 1] + s_bia[c0 + 1], 0.f);
                    uint32_t off = SWZ((uint32_t)row * 128 + (uint32_t)c0 * 2);
                    *(uint32_t*)(sm + XB0 + off) = pack_h2(f0, f1);
                }
            }
    } else {
        BAR_SYNC(BAR_FREE0);
        float4 dv = *(const float4*)&s_ds[p * 4];
        #pragma unroll
        for (int g = 0; g < 8; g++) {
            float f[8];
            #pragma unroll
            for (int j = 0; j < 8; j++) {
                int k = g * 8 + j;
                float4 w = *(const float4*)&s_wd0[k * 4];
                f[j] = fmaxf(dv.x * w.x + dv.y * w.y + dv.z * w.z + dv.w * w.w + s_bd0[k], 0.f);
            }
            uint4 v;
            v.x = pack_h2(f[0], f[1]); v.y = pack_h2(f[2], f[3]);
            v.z = pack_h2(f[4], f[5]); v.w = pack_h2(f[6], f[7]);
            uint32_t off = SWZ((uint32_t)p * 128 + g * 16);
            *(uint4*)(sm + XB1 + off) = v;
        }
        s_pv[p] = valid ? pool_val[p0 + p] : 0.f;
        s_pr[p] = valid ? pool_row[p0 + p] : 0;
    }
    __syncthreads();

    // ===================== epilogue phase B ==================================
    float acc2[2][8][4];
    if (warp < 4) {
        #pragma unroll
        for (int m = 0; m < 2; m++)
            #pragma unroll
            for (int n = 0; n < 8; n++)
                #pragma unroll
                for (int j = 0; j < 4; j++) acc2[m][n][j] = 0.f;
        gemm_tile<4>(acc2, SB + XB0, g_W2f, 0, rbase, lane);
    } else {
        float4 dv = *(const float4*)&s_ds[p * 4];
        #pragma unroll
        for (int g = 0; g < 8; g++) {
            float f[8];
            #pragma unroll
            for (int j = 0; j < 8; j++) {
                int k = 64 + g * 8 + j;
                float4 w = *(const float4*)&s_wd0[k * 4];
                f[j] = fmaxf(dv.x * w.x + dv.y * w.y + dv.z * w.z + dv.w * w.w + s_bd0[k], 0.f);
            }
            uint4 v;
            v.x = pack_h2(f[0], f[1]); v.y = pack_h2(f[2], f[3]);
            v.z = pack_h2(f[4], f[5]); v.w = pack_h2(f[6], f[7]);
            uint32_t off = SWZ((uint32_t)p * 128 + g * 16);
            *(uint4*)(sm + XB2 + off) = v;
        }
    }
    __syncthreads();

    // ===================== epilogue phase C: gate, combine, scatter ==========
    if (warp < 4) {
        #pragma unroll
        for (int half = 0; half < 2; half++) {
            float acc3[2][4][4];
            #pragma unroll
            for (int m = 0; m < 2; m++)
                #pragma unroll
                for (int n = 0; n < 4; n++)
                    #pragma unroll
                    for (int j = 0; j < 4; j++) acc3[m][n][j] = 0.f;
            gemm_tile<2>(acc3, SB + XB1, g_W3f, half * 2, rbase, lane);        // t0 x W3 chunk0
            gemm_tile<2>(acc3, SB + XB2, g_W3f + 512, half * 2, rbase, lane);  // t1 x W3 chunk1
            #pragma unroll
            for (int mt = 0; mt < 2; mt++)
                #pragma unroll
                for (int fn = 0; fn < 4; fn++) {
                    int nf = half * 4 + fn;
                    int c0 = nf * 8 + (lane & 3) * 2;
                    #pragma unroll
                    for (int pr2 = 0; pr2 < 2; pr2++) {
                        int row = rbase + mt * 16 + (lane >> 2) + pr2 * 8;
                        if (p0 + row < P_PERM) {
                            float pv = s_pv[row];
                            int pr = s_pr[row];
                            float h2a = acc2[mt][nf][pr2 * 2 + 0] + s_bli[c0];
                            float h2b = acc2[mt][nf][pr2 * 2 + 1] + s_bli[c0 + 1];
                            float ga  = acc3[mt][fn][pr2 * 2 + 0] + s_bd1[c0];
                            float gb  = acc3[mt][fn][pr2 * 2 + 1] + s_bd1[c0 + 1];
                            atomicAdd(&out[((size_t)pr << 6) + c0],     pv * h2a * ga);
                            atomicAdd(&out[((size_t)pr << 6) + c0 + 1], pv * h2b * gb);
                        }
                    }
                }
        }
    }
}

// ============================================================================
extern "C" void kernel_launch(void* const* d_in, const int* in_sizes, int n_in,
                              void* d_out, int out_size) {
    const float* nfeat         = (const float*)d_in[0];
    const float* degs          = (const float*)d_in[1];
    const float* n2p_val       = (const float*)d_in[2];
    const float* e2p_val       = (const float*)d_in[3];
    const float* pool_val      = (const float*)d_in[4];
    const float* weights       = (const float*)d_in[5];
    const float* bias          = (const float*)d_in[6];
    const float* w_deg0        = (const float*)d_in[7];
    const float* b_deg0        = (const float*)d_in[8];
    const float* w_deg1        = (const float*)d_in[9];
    const float* b_deg1        = (const float*)d_in[10];
    const float* w_lin         = (const float*)d_in[11];
    const float* b_lin         = (const float*)d_in[12];
    const float* bond_emb      = (const float*)d_in[13];
    const int*   edge_feat_idx = (const int*)d_in[14];
    const int*   n2p_col       = (const int*)d_in[16];
    const int*   e2p_col       = (const int*)d_in[18];
    const int*   pool_row      = (const int*)d_in[19];
    float* out = (float*)d_out;

    cudaMemsetAsync(d_out, 0, (size_t)out_size * sizeof(float), 0);
    prep_kernel<<<(8192 + N_NODES * 8 + 255) / 256, 256>>>(weights, w_lin, w_deg1, nfeat);

    cudaFuncSetAttribute(fused_kernel, cudaFuncAttributeMaxDynamicSharedMemorySize, SMEM_BYTES);
    fused_kernel<<<NTILES, 256, SMEM_BYTES>>>(degs, n2p_val, e2p_val, pool_val,
                                              bias, w_deg0, b_deg0, b_deg1, b_lin,
                                              bond_emb, edge_feat_idx, n2p_col, e2p_col,
                                              pool_row, out);
}

// round 15
// speedup vs baseline: 1.0481x; 1.0481x over previous
#include <cuda_runtime.h>
#include <cuda_fp16.h>
#include <cstdint>

#define P_PERM  200000
#define N_NODES 100000
#define PT      128
#define NTILES  ((P_PERM + PT - 1) / PT)
#define FULLM   0xffffffffu

#define SWZ(o) ((o) ^ (((o) >> 3) & 0x70))

// named barrier ids (0 = __syncthreads)
#define BAR_FREE0 1
#define BAR_FREE1 2
#define BAR_FULL0 3
#define BAR_FULL1 4
#define BAR_SYNC(id)   asm volatile("bar.sync %0, 256;"   :: "r"(id) : "memory")
#define BAR_ARRIVE(id) asm volatile("bar.arrive %0, 256;" :: "r"(id) : "memory")

// B operands pre-packed in fp16 mma fragment layout.
__device__ __align__(16) uint4 g_W1f[16 * 4 * 4 * 32];  // einsum weights, 128KB
__device__ __align__(16) uint4 g_W2f[4 * 4 * 32];       // w_lin, 8KB
__device__ __align__(16) uint4 g_W3f[2 * 4 * 4 * 32];   // w_deg1 (2 k-chunks), 16KB
// nfeat converted to fp16: row-major, 8 uint4 per row (64 fp16 = 128B)
__device__ __align__(16) uint4 g_nfh[(size_t)N_NODES * 8];   // 12.8MB

// ---------------------------- SMEM layout (bytes) ---------------------------
#define XB0   0        // four 16KB fp16 X tiles (128x64)
#define XB1   16384
#define XB2   32768
#define XB3   49152
#define SBOND 65536    // 512B: bond_emb fp16, uint4[32]
#define SDS   66048    // 512 f
#define SWD0  68096    // 512 f
#define SBD0  70144    // 128 f
#define SBIA  70656    // 64 f
#define SBLI  70912    // 64 f
#define SBD1  71168    // 64 f
#define SPV   71424    // 128 f
#define SPR   71936    // 128 i
#define SMEM_BYTES 72448

// ------------------------------ asm helpers --------------------------------
__device__ __forceinline__ void ldm_x4(uint32_t* r, uint32_t a) {
    asm volatile("ldmatrix.sync.aligned.m8n8.x4.shared.b16 {%0,%1,%2,%3}, [%4];"
                 : "=r"(r[0]), "=r"(r[1]), "=r"(r[2]), "=r"(r[3]) : "r"(a));
}
__device__ __forceinline__ void mma16816(float* d, const uint32_t* a, uint32_t b0, uint32_t b1) {
    asm volatile(
        "mma.sync.aligned.m16n8k16.row.col.f32.f16.f16.f32 "
        "{%0,%1,%2,%3}, {%4,%5,%6,%7}, {%8,%9}, {%0,%1,%2,%3};"
        : "+f"(d[0]), "+f"(d[1]), "+f"(d[2]), "+f"(d[3])
        : "r"(a[0]), "r"(a[1]), "r"(a[2]), "r"(a[3]), "r"(b0), "r"(b1));
}
__device__ __forceinline__ uint32_t s2u(const void* p) {
    uint32_t a;
    asm("{ .reg .u64 t; cvta.to.shared.u64 t, %1; cvt.u32.u64 %0, t; }" : "=r"(a) : "l"(p));
    return a;
}
__device__ __forceinline__ uint32_t pack_h2(float a, float b) {
    __half2 h = __floats2half2_rn(a, b);
    return *(uint32_t*)&h;
}

// ---- m32 x n(16*NFP) warp GEMM over K=64, single fp16 term ------------------
template<int NFP>
__device__ __forceinline__ void gemm_tile(float (&acc)[2][2 * NFP][4], uint32_t xh,
                                          const uint4* __restrict__ wf, int nfp0,
                                          int rbase, int lane) {
    const int sub = lane >> 3, rin = lane & 7;
    const uint32_t aRow = (uint32_t)(rbase + ((sub & 1) << 3) + rin) * 128;
    const uint32_t aCol = (uint32_t)((sub >> 1) << 4);
    #pragma unroll
    for (int kc = 0; kc < 4; kc++) {
        uint32_t aoff = SWZ(aRow + aCol + kc * 32);
        uint32_t ah0[4], ah1[4];
        ldm_x4(ah0, xh + aoff);
        ldm_x4(ah1, xh + aoff + 2048);   // +16 rows
        uint4 bfr[NFP];
        #pragma unroll
        for (int pg = 0; pg < NFP; pg++)
            bfr[pg] = wf[(kc * 4 + nfp0 + pg) * 32 + lane];
        #pragma unroll
        for (int pg = 0; pg < NFP; pg++) {
            mma16816(acc[0][2 * pg + 0], ah0, bfr[pg].x, bfr[pg].y);
            mma16816(acc[1][2 * pg + 0], ah1, bfr[pg].x, bfr[pg].y);
            mma16816(acc[0][2 * pg + 1], ah0, bfr[pg].z, bfr[pg].w);
            mma16816(acc[1][2 * pg + 1], ah1, bfr[pg].z, bfr[pg].w);
        }
    }
}

// ============================================================================
// prep: build fp16 B-fragment tables + fp16 nfeat table
// ============================================================================
__global__ void prep_kernel(const float* __restrict__ weights,
                            const float* __restrict__ w_lin,
                            const float* __restrict__ w_deg1,
                            const float* __restrict__ nfeat) {
    int idx = blockIdx.x * 256 + threadIdx.x;
    if (idx < 8192) {
        const int lane = idx & 31;
        const int nfp  = (idx >> 5) & 3;
        const int kc   = (idx >> 7) & 3;
        const int ce = nfp * 16 + (lane >> 2);
        const int co = ce + 8;
        const int kb = kc * 16 + (lane & 3) * 2;
        {
            int a = idx >> 9;
            uint4 v;
            v.x = pack_h2(weights[(((kb + 0) << 6) + ce) * 16 + a],
                          weights[(((kb + 1) << 6) + ce) * 16 + a]);
            v.y = pack_h2(weights[(((kb + 8) << 6) + ce) * 16 + a],
                          weights[(((kb + 9) << 6) + ce) * 16 + a]);
            v.z = pack_h2(weights[(((kb + 0) << 6) + co) * 16 + a],
                          weights[(((kb + 1) << 6) + co) * 16 + a]);
            v.w = pack_h2(weights[(((kb + 8) << 6) + co) * 16 + a],
                          weights[(((kb + 9) << 6) + co) * 16 + a]);
            g_W1f[idx] = v;
        }
        if (idx < 512) {
            const float* se = w_lin + ce * 64;
            const float* so = w_lin + co * 64;
            uint4 v;
            v.x = pack_h2(se[kb], se[kb + 1]);
            v.y = pack_h2(se[kb + 8], se[kb + 9]);
            v.z = pack_h2(so[kb], so[kb + 1]);
            v.w = pack_h2(so[kb + 8], so[kb + 9]);
            g_W2f[idx] = v;
        }
        if (idx < 1024) {
            int ch = idx >> 9;
            const float* se = w_deg1 + ce * 128 + ch * 64;
            const float* so = w_deg1 + co * 128 + ch * 64;
            uint4 v;
            v.x = pack_h2(se[kb], se[kb + 1]);
            v.y = pack_h2(se[kb + 8], se[kb + 9]);
            v.z = pack_h2(so[kb], so[kb + 1]);
            v.w = pack_h2(so[kb + 8], so[kb + 9]);
            g_W3f[idx] = v;
        }
    } else {
        int j = idx - 8192;                 // 0 .. N_NODES*8-1
        if (j < N_NODES * 8) {
            const float4* src = (const float4*)(nfeat) + (size_t)j * 2;
            float4 a = src[0], b = src[1];
            uint4 v;
            v.x = pack_h2(a.x, a.y); v.y = pack_h2(a.z, a.w);
            v.z = pack_h2(b.x, b.y); v.w = pack_h2(b.z, b.w);
            g_nfh[j] = v;
        }
    }
}

// ============================================================================
// fused: warp-specialized, fp16, decoupled named-barrier pipeline (4 buffers)
// ============================================================================
__global__ __launch_bounds__(256, 2)
void fused_kernel(const float* __restrict__ degs,
                  const float* __restrict__ n2p_val,
                  const float* __restrict__ e2p_val,
                  const float* __restrict__ pool_val,
                  const float* __restrict__ bias,
                  const float* __restrict__ w_deg0,
                  const float* __restrict__ b_deg0,
                  const float* __restrict__ b_deg1,
                  const float* __restrict__ b_lin,
                  const float* __restrict__ bond_emb,
                  const int*   __restrict__ edge_feat_idx,
                  const int*   __restrict__ n2p_col,
                  const int*   __restrict__ e2p_col,
                  const int*   __restrict__ pool_row,
                  float*       __restrict__ out) {
    extern __shared__ char sm[];
    const uint32_t SB = s2u(sm);
    const int tid = threadIdx.x;
    const int warp = tid >> 5, lane = tid & 31;
    const int p0 = blockIdx.x * PT;

    uint4* s_bondh = (uint4*)(sm + SBOND);
    float* s_ds   = (float*)(sm + SDS);
    float* s_wd0  = (float*)(sm + SWD0);
    float* s_bd0  = (float*)(sm + SBD0);
    float* s_bia  = (float*)(sm + SBIA);
    float* s_bli  = (float*)(sm + SBLI);
    float* s_bd1  = (float*)(sm + SBD1);
    float* s_pv   = (float*)(sm + SPV);
    int*   s_pr   = (int*)(sm + SPR);

    if (tid < 32) {   // bond_emb -> fp16, 4 rows x 8 uint4
        int row = tid >> 3, c8 = tid & 7;
        const float* s = bond_emb + row * 64 + c8 * 8;
        uint4 v;
        v.x = pack_h2(s[0], s[1]); v.y = pack_h2(s[2], s[3]);
        v.z = pack_h2(s[4], s[5]); v.w = pack_h2(s[6], s[7]);
        s_bondh[tid] = v;
    }
    for (int i = tid; i < 512; i += 256) s_wd0[i] = w_deg0[i];
    if (tid < 128) s_bd0[tid] = b_deg0[tid];
    if (tid < 64) { s_bia[tid] = bias[tid]; s_bli[tid] = b_lin[tid]; s_bd1[tid] = b_deg1[tid]; }
    __syncthreads();

    const int rbase = (warp & 3) * 32;

    float acc1[2][8][4];
    #pragma unroll
    for (int m = 0; m < 2; m++)
        #pragma unroll
        for (int n = 0; n < 8; n++)
            #pragma unroll
            for (int j = 0; j < 4; j++) acc1[m][n][j] = 0.f;

    const int p = tid - 128;                 // producer row id (warp>=4)
    const bool valid = (p0 + p) < P_PERM;
    const int pc = valid ? (p0 + p) : (P_PERM - 1);

    int ncs[4], bjs[4];
    float vns[4], ves[4];

    // ======== mainloop: 8 epochs x 2 slices, decoupled named barriers ========
    // pair b (buffers 2b,2b+1) filled at epoch e (b=e&1), consumed at e+1.
    #pragma unroll
    for (int e = 0; e < 8; e++) {
        if (warp >= 4) {
            const int b = e & 1;
            if (b == 0) {                    // load 4-slice index group + prefetch bj
                int g = e >> 1;
                int4 nc4 = ((const int4*)n2p_col)[pc * 4 + g];
                int4 ec4 = ((const int4*)e2p_col)[pc * 4 + g];
                float4 vn4 = ((const float4*)n2p_val)[pc * 4 + g];
                float4 ve4 = ((const float4*)e2p_val)[pc * 4 + g];
                ncs[0] = nc4.x; ncs[1] = nc4.y; ncs[2] = nc4.z; ncs[3] = nc4.w;
                vns[0] = vn4.x; vns[1] = vn4.y; vns[2] = vn4.z; vns[3] = vn4.w;
                ves[0] = ve4.x; ves[1] = ve4.y; ves[2] = ve4.z; ves[3] = ve4.w;
                bjs[0] = edge_feat_idx[ec4.x];   // 4 independent dependent-loads,
                bjs[1] = edge_feat_idx[ec4.y];   // overlapped here instead of
                bjs[2] = edge_feat_idx[ec4.z];   // serializing one per slice
                bjs[3] = edge_feat_idx[ec4.w];
            }
            if (e >= 2) BAR_SYNC(BAR_FREE0 + b);   // wait pair free
            #pragma unroll
            for (int s = 0; s < 2; s++) {
                const int a = 2 * e + s;
                const int ai = a & 3;
                int nc = ncs[ai];
                int bj = bjs[ai];
                float vn = valid ? vns[ai] : 0.f;
                float ve = valid ? ves[ai] : 0.f;
                if (ai == (a >> 2)) s_ds[p * 4 + (a >> 2)] = vn * degs[nc]; // a%5==0
                char* xh = sm + (2 * b + s) * 16384;
                const int r0 = (warp - 4) * 32;
                #pragma unroll
                for (int pass = 0; pass < 8; pass++) {
                    int src = pass * 4 + (lane >> 3);
                    int   nc_r = __shfl_sync(FULLM, nc, src);
                    int   bj_r = __shfl_sync(FULLM, bj, src);
                    float vn_r = __shfl_sync(FULLM, vn, src);
                    float ve_r = __shfl_sync(FULLM, ve, src);
                    int row = r0 + pass * 4 + (lane >> 3);
                    uint4 nv = g_nfh[(size_t)nc_r * 8 + (lane & 7)];     // 1 LDG.128
                    uint4 bv = s_bondh[bj_r * 8 + (lane & 7)];           // 1 LDS.128
                    __half2 vn2 = __float2half2_rn(vn_r);
                    __half2 ve2 = __float2half2_rn(ve_r);
                    uint4 v;
                    *(__half2*)&v.x = __hfma2(vn2, *(const __half2*)&nv.x,
                                              __hmul2(ve2, *(const __half2*)&bv.x));
                    *(__half2*)&v.y = __hfma2(vn2, *(const __half2*)&nv.y,
                                              __hmul2(ve2, *(const __half2*)&bv.y));
                    *(__half2*)&v.z = __hfma2(vn2, *(const __half2*)&nv.z,
                                              __hmul2(ve2, *(const __half2*)&bv.z));
                    *(__half2*)&v.w = __hfma2(vn2, *(const __half2*)&nv.w,
                                              __hmul2(ve2, *(const __half2*)&bv.w));
                    uint32_t off = SWZ((uint32_t)row * 128 + ((lane & 7) << 4));
                    *(uint4*)(xh + off) = v;
                }
            }
            BAR_ARRIVE(BAR_FULL0 + b);             // pair filled
        } else if (e > 0) {
            const int b = (e - 1) & 1;
            BAR_SYNC(BAR_FULL0 + b);               // wait pair full
            #pragma unroll
            for (int s = 0; s < 2; s++) {
                const int a = 2 * (e - 1) + s;
                gemm_tile<4>(acc1, SB + (2 * b + s) * 16384, g_W1f + a * 512, 0, rbase, lane);
            }
            BAR_ARRIVE(BAR_FREE0 + b);             // pair free
        }
    }

    // ===================== epilogue phase A ==================================
    // consumers: sync FULL1, gemm slices 14 (XB2), 15 (XB3); relu(acc1+bias)->XB0 (own rows)
    // producers: sync FREE0, t0 -> XB1, pool staging
    if (warp < 4) {
        BAR_SYNC(BAR_FULL1);
        gemm_tile<4>(acc1, SB + XB2, g_W1f + 14 * 512, 0, rbase, lane);
        gemm_tile<4>(acc1, SB + XB3, g_W1f + 15 * 512, 0, rbase, lane);
        #pragma unroll
        for (int mt = 0; mt < 2; mt++)
            #pragma unroll
            for (int nf = 0; nf < 8; nf++) {
                int c0 = nf * 8 + (lane & 3) * 2;
                #pragma unroll
                for (int pr2 = 0; pr2 < 2; pr2++) {
                    int row = rbase + mt * 16 + (lane >> 2) + pr2 * 8;
                    float f0 = fmaxf(acc1[mt][nf][pr2 * 2 + 0] + s_bia[c0], 0.f);
                    float f1 = fmaxf(acc1[mt][nf][pr2 * 2 + 1] + s_bia[c0 + 1], 0.f);
                    uint32_t off = SWZ((uint32_t)row * 128 + (uint32_t)c0 * 2);
                    *(uint32_t*)(sm + XB0 + off) = pack_h2(f0, f1);
                }
            }
    } else {
        BAR_SYNC(BAR_FREE0);
        float4 dv = *(const float4*)&s_ds[p * 4];
        #pragma unroll
        for (int g = 0; g < 8; g++) {
            float f[8];
            #pragma unroll
            for (int j = 0; j < 8; j++) {
                int k = g * 8 + j;
                float4 w = *(const float4*)&s_wd0[k * 4];
                f[j] = fmaxf(dv.x * w.x + dv.y * w.y + dv.z * w.z + dv.w * w.w + s_bd0[k], 0.f);
            }
            uint4 v;
            v.x = pack_h2(f[0], f[1]); v.y = pack_h2(f[2], f[3]);
            v.z = pack_h2(f[4], f[5]); v.w = pack_h2(f[6], f[7]);
            uint32_t off = SWZ((uint32_t)p * 128 + g * 16);
            *(uint4*)(sm + XB1 + off) = v;
        }
        s_pv[p] = valid ? pool_val[p0 + p] : 0.f;
        s_pr[p] = valid ? pool_row[p0 + p] : 0;
    }
    __syncthreads();

    // ===================== epilogue phase B ==================================
    // consumers: acc2 = relu(h) @ W2^T (reads XB0 own rows); producers: t1 -> XB2
    float acc2[2][8][4];
    if (warp < 4) {
        #pragma unroll
        for (int m = 0; m < 2; m++)
            #pragma unroll
            for (int n = 0; n < 8; n++)
                #pragma unroll
                for (int j = 0; j < 4; j++) acc2[m][n][j] = 0.f;
        gemm_tile<4>(acc2, SB + XB0, g_W2f, 0, rbase, lane);
    } else {
        float4 dv = *(const float4*)&s_ds[p * 4];
        #pragma unroll
        for (int g = 0; g < 8; g++) {
            float f[8];
            #pragma unroll
            for (int j = 0; j < 8; j++) {
                int k = 64 + g * 8 + j;
                float4 w = *(const float4*)&s_wd0[k * 4];
                f[j] = fmaxf(dv.x * w.x + dv.y * w.y + dv.z * w.z + dv.w * w.w + s_bd0[k], 0.f);
            }
            uint4 v;
            v.x = pack_h2(f[0], f[1]); v.y = pack_h2(f[2], f[3]);
            v.z = pack_h2(f[4], f[5]); v.w = pack_h2(f[6], f[7]);
            uint32_t off = SWZ((uint32_t)p * 128 + g * 16);
            *(uint4*)(sm + XB2 + off) = v;
        }
    }
    __syncthreads();

    // ===================== epilogue phase C: gate, combine, scatter ==========
    if (warp < 4) {
        #pragma unroll
        for (int half = 0; half < 2; half++) {
            float acc3[2][4][4];
            #pragma unroll
            for (int m = 0; m < 2; m++)
                #pragma unroll
                for (int n = 0; n < 4; n++)
                    #pragma unroll
                    for (int j = 0; j < 4; j++) acc3[m][n][j] = 0.f;
            gemm_tile<2>(acc3, SB + XB1, g_W3f, half * 2, rbase, lane);        // t0 x W3 chunk0
            gemm_tile<2>(acc3, SB + XB2, g_W3f + 512, half * 2, rbase, lane);  // t1 x W3 chunk1
            #pragma unroll
            for (int mt = 0; mt < 2; mt++)
                #pragma unroll
                for (int fn = 0; fn < 4; fn++) {
                    int nf = half * 4 + fn;
                    int c0 = nf * 8 + (lane & 3) * 2;
                    #pragma unroll
                    for (int pr2 = 0; pr2 < 2; pr2++) {
                        int row = rbase + mt * 16 + (lane >> 2) + pr2 * 8;
                        if (p0 + row < P_PERM) {
                            float pv = s_pv[row];
                            int pr = s_pr[row];
                            float h2a = acc2[mt][nf][pr2 * 2 + 0] + s_bli[c0];
                            float h2b = acc2[mt][nf][pr2 * 2 + 1] + s_bli[c0 + 1];
                            float ga  = acc3[mt][fn][pr2 * 2 + 0] + s_bd1[c0];
                            float gb  = acc3[mt][fn][pr2 * 2 + 1] + s_bd1[c0 + 1];
                            atomicAdd(&out[((size_t)pr << 6) + c0],     pv * h2a * ga);
                            atomicAdd(&out[((size_t)pr << 6) + c0 + 1], pv * h2b * gb);
                        }
                    }
                }
        }
    }
}

// ============================================================================
extern "C" void kernel_launch(void* const* d_in, const int* in_sizes, int n_in,
                              void* d_out, int out_size) {
    const float* nfeat         = (const float*)d_in[0];
    const float* degs          = (const float*)d_in[1];
    const float* n2p_val       = (const float*)d_in[2];
    const float* e2p_val       = (const float*)d_in[3];
    const float* pool_val      = (const float*)d_in[4];
    const float* weights       = (const float*)d_in[5];
    const float* bias          = (const float*)d_in[6];
    const float* w_deg0        = (const float*)d_in[7];
    const float* b_deg0        = (const float*)d_in[8];
    const float* w_deg1        = (const float*)d_in[9];
    const float* b_deg1        = (const float*)d_in[10];
    const float* w_lin         = (const float*)d_in[11];
    const float* b_lin         = (const float*)d_in[12];
    const float* bond_emb      = (const float*)d_in[13];
    const int*   edge_feat_idx = (const int*)d_in[14];
    const int*   n2p_col       = (const int*)d_in[16];
    const int*   e2p_col       = (const int*)d_in[18];
    const int*   pool_row      = (const int*)d_in[19];
    float* out = (float*)d_out;

    cudaMemsetAsync(d_out, 0, (size_t)out_size * sizeof(float), 0);
    prep_kernel<<<(8192 + N_NODES * 8 + 255) / 256, 256>>>(weights, w_lin, w_deg1, nfeat);

    cudaFuncSetAttribute(fused_kernel, cudaFuncAttributeMaxDynamicSharedMemorySize, SMEM_BYTES);
    fused_kernel<<<NTILES, 256, SMEM_BYTES>>>(degs, n2p_val, e2p_val, pool_val,
                                              bias, w_deg0, b_deg0, b_deg1, b_lin,
                                              bond_emb, edge_feat_idx, n2p_col, e2p_col,
                                              pool_row, out);
}

// round 16
// speedup vs baseline: 1.0742x; 1.0248x over previous
#include <cuda_runtime.h>
#include <cuda_fp16.h>
#include <cstdint>

#define P_PERM  200000
#define N_NODES 100000
#define PT      128
#define NTILES  ((P_PERM + PT - 1) / PT)
#define FULLM   0xffffffffu

#define SWZ(o) ((o) ^ (((o) >> 3) & 0x70))

// named barrier ids (0 = __syncthreads)
#define BAR_FREE0 1
#define BAR_FREE1 2
#define BAR_FULL0 3
#define BAR_FULL1 4
#define BAR_SYNC(id)   asm volatile("bar.sync %0, 256;"   :: "r"(id) : "memory")
#define BAR_ARRIVE(id) asm volatile("bar.arrive %0, 256;" :: "r"(id) : "memory")

// B operands pre-packed in fp16 mma fragment layout.
__device__ __align__(16) uint4 g_W1f[16 * 4 * 4 * 32];  // einsum weights, 128KB
__device__ __align__(16) uint4 g_W2f[4 * 4 * 32];       // w_lin, 8KB
__device__ __align__(16) uint4 g_W3f[2 * 4 * 4 * 32];   // w_deg1 (2 k-chunks), 16KB
// nfeat converted to fp16: row-major, 8 uint4 per row (64 fp16 = 128B)
__device__ __align__(16) uint4 g_nfh[(size_t)N_NODES * 8];   // 12.8MB

// ---------------------------- SMEM layout (bytes) ---------------------------
#define XB0   0        // four 16KB fp16 X tiles (128x64)
#define XB1   16384
#define XB2   32768
#define XB3   49152
#define SBOND 65536    // 512B: bond_emb fp16, uint4[32]
#define SDS   66048    // 512 f
#define SWD0  68096    // 512 f
#define SBD0  70144    // 128 f
#define SBIA  70656    // 64 f
#define SBLI  70912    // 64 f
#define SBD1  71168    // 64 f
#define SPV   71424    // 128 f
#define SPR   71936    // 128 i
#define SMEM_BYTES 72448

// ------------------------------ asm helpers --------------------------------
__device__ __forceinline__ void ldm_x4(uint32_t* r, uint32_t a) {
    asm volatile("ldmatrix.sync.aligned.m8n8.x4.shared.b16 {%0,%1,%2,%3}, [%4];"
                 : "=r"(r[0]), "=r"(r[1]), "=r"(r[2]), "=r"(r[3]) : "r"(a));
}
__device__ __forceinline__ void mma16816(float* d, const uint32_t* a, uint32_t b0, uint32_t b1) {
    asm volatile(
        "mma.sync.aligned.m16n8k16.row.col.f32.f16.f16.f32 "
        "{%0,%1,%2,%3}, {%4,%5,%6,%7}, {%8,%9}, {%0,%1,%2,%3};"
        : "+f"(d[0]), "+f"(d[1]), "+f"(d[2]), "+f"(d[3])
        : "r"(a[0]), "r"(a[1]), "r"(a[2]), "r"(a[3]), "r"(b0), "r"(b1));
}
__device__ __forceinline__ uint32_t s2u(const void* p) {
    uint32_t a;
    asm("{ .reg .u64 t; cvta.to.shared.u64 t, %1; cvt.u32.u64 %0, t; }" : "=r"(a) : "l"(p));
    return a;
}
__device__ __forceinline__ uint32_t pack_h2(float a, float b) {
    __half2 h = __floats2half2_rn(a, b);
    return *(uint32_t*)&h;
}
// vectorized no-return float2 reduction (sm_90+, base ISA feature)
__device__ __forceinline__ void red_add_v2(float* ptr, float a, float b) {
    asm volatile("red.global.add.v2.f32 [%0], {%1, %2};"
                 :: "l"(ptr), "f"(a), "f"(b) : "memory");
}

// ---- m32 x n(16*NFP) warp GEMM over K=64, single fp16 term ------------------
template<int NFP>
__device__ __forceinline__ void gemm_tile(float (&acc)[2][2 * NFP][4], uint32_t xh,
                                          const uint4* __restrict__ wf, int nfp0,
                                          int rbase, int lane) {
    const int sub = lane >> 3, rin = lane & 7;
    const uint32_t aRow = (uint32_t)(rbase + ((sub & 1) << 3) + rin) * 128;
    const uint32_t aCol = (uint32_t)((sub >> 1) << 4);
    #pragma unroll
    for (int kc = 0; kc < 4; kc++) {
        uint32_t aoff = SWZ(aRow + aCol + kc * 32);
        uint32_t ah0[4], ah1[4];
        ldm_x4(ah0, xh + aoff);
        ldm_x4(ah1, xh + aoff + 2048);   // +16 rows
        uint4 bfr[NFP];
        #pragma unroll
        for (int pg = 0; pg < NFP; pg++)
            bfr[pg] = wf[(kc * 4 + nfp0 + pg) * 32 + lane];
        #pragma unroll
        for (int pg = 0; pg < NFP; pg++) {
            mma16816(acc[0][2 * pg + 0], ah0, bfr[pg].x, bfr[pg].y);
            mma16816(acc[1][2 * pg + 0], ah1, bfr[pg].x, bfr[pg].y);
            mma16816(acc[0][2 * pg + 1], ah0, bfr[pg].z, bfr[pg].w);
            mma16816(acc[1][2 * pg + 1], ah1, bfr[pg].z, bfr[pg].w);
        }
    }
}

// ============================================================================
// prep: build fp16 B-fragment tables + fp16 nfeat table
// ============================================================================
__global__ void prep_kernel(const float* __restrict__ weights,
                            const float* __restrict__ w_lin,
                            const float* __restrict__ w_deg1,
                            const float* __restrict__ nfeat) {
    int idx = blockIdx.x * 256 + threadIdx.x;
    if (idx < 8192) {
        const int lane = idx & 31;
        const int nfp  = (idx >> 5) & 3;
        const int kc   = (idx >> 7) & 3;
        const int ce = nfp * 16 + (lane >> 2);
        const int co = ce + 8;
        const int kb = kc * 16 + (lane & 3) * 2;
        {
            int a = idx >> 9;
            uint4 v;
            v.x = pack_h2(weights[(((kb + 0) << 6) + ce) * 16 + a],
                          weights[(((kb + 1) << 6) + ce) * 16 + a]);
            v.y = pack_h2(weights[(((kb + 8) << 6) + ce) * 16 + a],
                          weights[(((kb + 9) << 6) + ce) * 16 + a]);
            v.z = pack_h2(weights[(((kb + 0) << 6) + co) * 16 + a],
                          weights[(((kb + 1) << 6) + co) * 16 + a]);
            v.w = pack_h2(weights[(((kb + 8) << 6) + co) * 16 + a],
                          weights[(((kb + 9) << 6) + co) * 16 + a]);
            g_W1f[idx] = v;
        }
        if (idx < 512) {
            const float* se = w_lin + ce * 64;
            const float* so = w_lin + co * 64;
            uint4 v;
            v.x = pack_h2(se[kb], se[kb + 1]);
            v.y = pack_h2(se[kb + 8], se[kb + 9]);
            v.z = pack_h2(so[kb], so[kb + 1]);
            v.w = pack_h2(so[kb + 8], so[kb + 9]);
            g_W2f[idx] = v;
        }
        if (idx < 1024) {
            int ch = idx >> 9;
            const float* se = w_deg1 + ce * 128 + ch * 64;
            const float* so = w_deg1 + co * 128 + ch * 64;
            uint4 v;
            v.x = pack_h2(se[kb], se[kb + 1]);
            v.y = pack_h2(se[kb + 8], se[kb + 9]);
            v.z = pack_h2(so[kb], so[kb + 1]);
            v.w = pack_h2(so[kb + 8], so[kb + 9]);
            g_W3f[idx] = v;
        }
    } else {
        int j = idx - 8192;                 // 0 .. N_NODES*8-1
        if (j < N_NODES * 8) {
            const float4* src = (const float4*)(nfeat) + (size_t)j * 2;
            float4 a = src[0], b = src[1];
            uint4 v;
            v.x = pack_h2(a.x, a.y); v.y = pack_h2(a.z, a.w);
            v.z = pack_h2(b.x, b.y); v.w = pack_h2(b.z, b.w);
            g_nfh[j] = v;
        }
    }
}

// ============================================================================
// fused: warp-specialized, fp16, decoupled named-barrier pipeline (4 buffers)
// ============================================================================
__global__ __launch_bounds__(256, 2)
void fused_kernel(const float* __restrict__ degs,
                  const float* __restrict__ n2p_val,
                  const float* __restrict__ e2p_val,
                  const float* __restrict__ pool_val,
                  const float* __restrict__ bias,
                  const float* __restrict__ w_deg0,
                  const float* __restrict__ b_deg0,
                  const float* __restrict__ b_deg1,
                  const float* __restrict__ b_lin,
                  const float* __restrict__ bond_emb,
                  const int*   __restrict__ edge_feat_idx,
                  const int*   __restrict__ n2p_col,
                  const int*   __restrict__ e2p_col,
                  const int*   __restrict__ pool_row,
                  float*       __restrict__ out) {
    extern __shared__ char sm[];
    const uint32_t SB = s2u(sm);
    const int tid = threadIdx.x;
    const int warp = tid >> 5, lane = tid & 31;
    const int p0 = blockIdx.x * PT;

    uint4* s_bondh = (uint4*)(sm + SBOND);
    float* s_ds   = (float*)(sm + SDS);
    float* s_wd0  = (float*)(sm + SWD0);
    float* s_bd0  = (float*)(sm + SBD0);
    float* s_bia  = (float*)(sm + SBIA);
    float* s_bli  = (float*)(sm + SBLI);
    float* s_bd1  = (float*)(sm + SBD1);
    float* s_pv   = (float*)(sm + SPV);
    int*   s_pr   = (int*)(sm + SPR);

    if (tid < 32) {   // bond_emb -> fp16, 4 rows x 8 uint4
        int row = tid >> 3, c8 = tid & 7;
        const float* s = bond_emb + row * 64 + c8 * 8;
        uint4 v;
        v.x = pack_h2(s[0], s[1]); v.y = pack_h2(s[2], s[3]);
        v.z = pack_h2(s[4], s[5]); v.w = pack_h2(s[6], s[7]);
        s_bondh[tid] = v;
    }
    for (int i = tid; i < 512; i += 256) s_wd0[i] = w_deg0[i];
    if (tid < 128) s_bd0[tid] = b_deg0[tid];
    if (tid < 64) { s_bia[tid] = bias[tid]; s_bli[tid] = b_lin[tid]; s_bd1[tid] = b_deg1[tid]; }
    __syncthreads();

    const int rbase = (warp & 3) * 32;

    float acc1[2][8][4];
    #pragma unroll
    for (int m = 0; m < 2; m++)
        #pragma unroll
        for (int n = 0; n < 8; n++)
            #pragma unroll
            for (int j = 0; j < 4; j++) acc1[m][n][j] = 0.f;

    const int p = tid - 128;                 // producer row id (warp>=4)
    const bool valid = (p0 + p) < P_PERM;
    const int pc = valid ? (p0 + p) : (P_PERM - 1);

    int ncs[4], bjs[4];
    float vns[4], ves[4];

    // ======== mainloop: 8 epochs x 2 slices, decoupled named barriers ========
    // pair b (buffers 2b,2b+1) filled at epoch e (b=e&1), consumed at e+1.
    #pragma unroll
    for (int e = 0; e < 8; e++) {
        if (warp >= 4) {
            const int b = e & 1;
            if (b == 0) {                    // load 4-slice index group + prefetch bj
                int g = e >> 1;
                int4 nc4 = ((const int4*)n2p_col)[pc * 4 + g];
                int4 ec4 = ((const int4*)e2p_col)[pc * 4 + g];
                float4 vn4 = ((const float4*)n2p_val)[pc * 4 + g];
                float4 ve4 = ((const float4*)e2p_val)[pc * 4 + g];
                ncs[0] = nc4.x; ncs[1] = nc4.y; ncs[2] = nc4.z; ncs[3] = nc4.w;
                vns[0] = vn4.x; vns[1] = vn4.y; vns[2] = vn4.z; vns[3] = vn4.w;
                ves[0] = ve4.x; ves[1] = ve4.y; ves[2] = ve4.z; ves[3] = ve4.w;
                bjs[0] = edge_feat_idx[ec4.x];   // 4 independent dependent-loads,
                bjs[1] = edge_feat_idx[ec4.y];   // overlapped here instead of
                bjs[2] = edge_feat_idx[ec4.z];   // serializing one per slice
                bjs[3] = edge_feat_idx[ec4.w];
            }
            if (e >= 2) BAR_SYNC(BAR_FREE0 + b);   // wait pair free
            #pragma unroll
            for (int s = 0; s < 2; s++) {
                const int a = 2 * e + s;
                const int ai = a & 3;
                int nc = ncs[ai];
                int bj = bjs[ai];
                float vn = valid ? vns[ai] : 0.f;
                float ve = valid ? ves[ai] : 0.f;
                if (ai == (a >> 2)) s_ds[p * 4 + (a >> 2)] = vn * degs[nc]; // a%5==0
                char* xh = sm + (2 * b + s) * 16384;
                const int r0 = (warp - 4) * 32;
                #pragma unroll
                for (int pass = 0; pass < 8; pass++) {
                    int src = pass * 4 + (lane >> 3);
                    int   nc_r = __shfl_sync(FULLM, nc, src);
                    int   bj_r = __shfl_sync(FULLM, bj, src);
                    float vn_r = __shfl_sync(FULLM, vn, src);
                    float ve_r = __shfl_sync(FULLM, ve, src);
                    int row = r0 + pass * 4 + (lane >> 3);
                    uint4 nv = g_nfh[(size_t)nc_r * 8 + (lane & 7)];     // 1 LDG.128
                    uint4 bv = s_bondh[bj_r * 8 + (lane & 7)];           // 1 LDS.128
                    __half2 vn2 = __float2half2_rn(vn_r);
                    __half2 ve2 = __float2half2_rn(ve_r);
                    uint4 v;
                    *(__half2*)&v.x = __hfma2(vn2, *(const __half2*)&nv.x,
                                              __hmul2(ve2, *(const __half2*)&bv.x));
                    *(__half2*)&v.y = __hfma2(vn2, *(const __half2*)&nv.y,
                                              __hmul2(ve2, *(const __half2*)&bv.y));
                    *(__half2*)&v.z = __hfma2(vn2, *(const __half2*)&nv.z,
                                              __hmul2(ve2, *(const __half2*)&bv.z));
                    *(__half2*)&v.w = __hfma2(vn2, *(const __half2*)&nv.w,
                                              __hmul2(ve2, *(const __half2*)&bv.w));
                    uint32_t off = SWZ((uint32_t)row * 128 + ((lane & 7) << 4));
                    *(uint4*)(xh + off) = v;
                }
            }
            BAR_ARRIVE(BAR_FULL0 + b);             // pair filled
        } else if (e > 0) {
            const int b = (e - 1) & 1;
            BAR_SYNC(BAR_FULL0 + b);               // wait pair full
            #pragma unroll
            for (int s = 0; s < 2; s++) {
                const int a = 2 * (e - 1) + s;
                gemm_tile<4>(acc1, SB + (2 * b + s) * 16384, g_W1f + a * 512, 0, rbase, lane);
            }
            BAR_ARRIVE(BAR_FREE0 + b);             // pair free
        }
    }

    // ===================== epilogue phase A ==================================
    // consumers: sync FULL1, gemm slices 14 (XB2), 15 (XB3); relu(acc1+bias)->XB0 (own rows)
    // producers: sync FREE0, t0 -> XB1, pool staging
    if (warp < 4) {
        BAR_SYNC(BAR_FULL1);
        gemm_tile<4>(acc1, SB + XB2, g_W1f + 14 * 512, 0, rbase, lane);
        gemm_tile<4>(acc1, SB + XB3, g_W1f + 15 * 512, 0, rbase, lane);
        #pragma unroll
        for (int mt = 0; mt < 2; mt++)
            #pragma unroll
            for (int nf = 0; nf < 8; nf++) {
                int c0 = nf * 8 + (lane & 3) * 2;
                #pragma unroll
                for (int pr2 = 0; pr2 < 2; pr2++) {
                    int row = rbase + mt * 16 + (lane >> 2) + pr2 * 8;
                    float f0 = fmaxf(acc1[mt][nf][pr2 * 2 + 0] + s_bia[c0], 0.f);
                    float f1 = fmaxf(acc1[mt][nf][pr2 * 2 + 1] + s_bia[c0 + 1], 0.f);
                    uint32_t off = SWZ((uint32_t)row * 128 + (uint32_t)c0 * 2);
                    *(uint32_t*)(sm + XB0 + off) = pack_h2(f0, f1);
                }
            }
    } else {
        BAR_SYNC(BAR_FREE0);
        float4 dv = *(const float4*)&s_ds[p * 4];
        #pragma unroll
        for (int g = 0; g < 8; g++) {
            float f[8];
            #pragma unroll
            for (int j = 0; j < 8; j++) {
                int k = g * 8 + j;
                float4 w = *(const float4*)&s_wd0[k * 4];
                f[j] = fmaxf(dv.x * w.x + dv.y * w.y + dv.z * w.z + dv.w * w.w + s_bd0[k], 0.f);
            }
            uint4 v;
            v.x = pack_h2(f[0], f[1]); v.y = pack_h2(f[2], f[3]);
            v.z = pack_h2(f[4], f[5]); v.w = pack_h2(f[6], f[7]);
            uint32_t off = SWZ((uint32_t)p * 128 + g * 16);
            *(uint4*)(sm + XB1 + off) = v;
        }
        s_pv[p] = valid ? pool_val[p0 + p] : 0.f;
        s_pr[p] = valid ? pool_row[p0 + p] : 0;
    }
    __syncthreads();

    // ===================== epilogue phase B ==================================
    // consumers: acc2 = relu(h) @ W2^T (reads XB0 own rows); producers: t1 -> XB2
    float acc2[2][8][4];
    if (warp < 4) {
        #pragma unroll
        for (int m = 0; m < 2; m++)
            #pragma unroll
            for (int n = 0; n < 8; n++)
                #pragma unroll
                for (int j = 0; j < 4; j++) acc2[m][n][j] = 0.f;
        gemm_tile<4>(acc2, SB + XB0, g_W2f, 0, rbase, lane);
    } else {
        float4 dv = *(const float4*)&s_ds[p * 4];
        #pragma unroll
        for (int g = 0; g < 8; g++) {
            float f[8];
            #pragma unroll
            for (int j = 0; j < 8; j++) {
                int k = 64 + g * 8 + j;
                float4 w = *(const float4*)&s_wd0[k * 4];
                f[j] = fmaxf(dv.x * w.x + dv.y * w.y + dv.z * w.z + dv.w * w.w + s_bd0[k], 0.f);
            }
            uint4 v;
            v.x = pack_h2(f[0], f[1]); v.y = pack_h2(f[2], f[3]);
            v.z = pack_h2(f[4], f[5]); v.w = pack_h2(f[6], f[7]);
            uint32_t off = SWZ((uint32_t)p * 128 + g * 16);
            *(uint4*)(sm + XB2 + off) = v;
        }
    }
    __syncthreads();

    // ===================== epilogue phase C: gate, combine, scatter ==========
    if (warp < 4) {
        #pragma unroll
        for (int half = 0; half < 2; half++) {
            float acc3[2][4][4];
            #pragma unroll
            for (int m = 0; m < 2; m++)
                #pragma unroll
                for (int n = 0; n < 4; n++)
                    #pragma unroll
                    for (int j = 0; j < 4; j++) acc3[m][n][j] = 0.f;
            gemm_tile<2>(acc3, SB + XB1, g_W3f, half * 2, rbase, lane);        // t0 x W3 chunk0
            gemm_tile<2>(acc3, SB + XB2, g_W3f + 512, half * 2, rbase, lane);  // t1 x W3 chunk1
            #pragma unroll
            for (int mt = 0; mt < 2; mt++)
                #pragma unroll
                for (int fn = 0; fn < 4; fn++) {
                    int nf = half * 4 + fn;
                    int c0 = nf * 8 + (lane & 3) * 2;
                    #pragma unroll
                    for (int pr2 = 0; pr2 < 2; pr2++) {
                        int row = rbase + mt * 16 + (lane >> 2) + pr2 * 8;
                        if (p0 + row < P_PERM) {
                            float pv = s_pv[row];
                            int pr = s_pr[row];
                            float h2a = acc2[mt][nf][pr2 * 2 + 0] + s_bli[c0];
                            float h2b = acc2[mt][nf][pr2 * 2 + 1] + s_bli[c0 + 1];
                            float ga  = acc3[mt][fn][pr2 * 2 + 0] + s_bd1[c0];
                            float gb  = acc3[mt][fn][pr2 * 2 + 1] + s_bd1[c0 + 1];
                            red_add_v2(&out[((size_t)pr << 6) + c0],
                                       pv * h2a * ga, pv * h2b * gb);
                        }
                    }
                }
        }
    }
}

// ============================================================================
extern "C" void kernel_launch(void* const* d_in, const int* in_sizes, int n_in,
                              void* d_out, int out_size) {
    const float* nfeat         = (const float*)d_in[0];
    const float* degs          = (const float*)d_in[1];
    const float* n2p_val       = (const float*)d_in[2];
    const float* e2p_val       = (const float*)d_in[3];
    const float* pool_val      = (const float*)d_in[4];
    const float* weights       = (const float*)d_in[5];
    const float* bias          = (const float*)d_in[6];
    const float* w_deg0        = (const float*)d_in[7];
    const float* b_deg0        = (const float*)d_in[8];
    const float* w_deg1        = (const float*)d_in[9];
    const float* b_deg1        = (const float*)d_in[10];
    const float* w_lin         = (const float*)d_in[11];
    const float* b_lin         = (const float*)d_in[12];
    const float* bond_emb      = (const float*)d_in[13];
    const int*   edge_feat_idx = (const int*)d_in[14];
    const int*   n2p_col       = (const int*)d_in[16];
    const int*   e2p_col       = (const int*)d_in[18];
    const int*   pool_row      = (const int*)d_in[19];
    float* out = (float*)d_out;

    cudaMemsetAsync(d_out, 0, (size_t)out_size * sizeof(float), 0);
    prep_kernel<<<(8192 + N_NODES * 8 + 255) / 256, 256>>>(weights, w_lin, w_deg1, nfeat);

    cudaFuncSetAttribute(fused_kernel, cudaFuncAttributeMaxDynamicSharedMemorySize, SMEM_BYTES);
    fused_kernel<<<NTILES, 256, SMEM_BYTES>>>(degs, n2p_val, e2p_val, pool_val,
                                              bias, w_deg0, b_deg0, b_deg1, b_lin,
                                              bond_emb, edge_feat_idx, n2p_col, e2p_col,
                                              pool_row, out);
}

// round 17
// speedup vs baseline: 1.0861x; 1.0111x over previous
#include <cuda_runtime.h>
#include <cuda_fp16.h>
#include <cstdint>

#define P_PERM  200000
#define N_NODES 100000
#define PT      128
#define NTILES  ((P_PERM + PT - 1) / PT)
#define FULLM   0xffffffffu

#define SWZ(o) ((o) ^ (((o) >> 3) & 0x70))

// named barrier ids (0 = __syncthreads)
#define BAR_FREE0 1
#define BAR_FREE1 2
#define BAR_FULL0 3
#define BAR_FULL1 4
#define BAR_SYNC(id)   asm volatile("bar.sync %0, 256;"   :: "r"(id) : "memory")
#define BAR_ARRIVE(id) asm volatile("bar.arrive %0, 256;" :: "r"(id) : "memory")

// B operands pre-packed in fp16 mma fragment layout.
__device__ __align__(16) uint4 g_W1f[16 * 4 * 4 * 32];  // einsum weights, 128KB
__device__ __align__(16) uint4 g_W2f[4 * 4 * 32];       // w_lin, 8KB
__device__ __align__(16) uint4 g_W3f[2 * 4 * 4 * 32];   // w_deg1 (2 k-chunks), 16KB
// nfeat converted to fp16: row-major, 8 uint4 per row (64 fp16 = 128B)
__device__ __align__(16) uint4 g_nfh[(size_t)N_NODES * 8];   // 12.8MB

// ---------------------------- SMEM layout (bytes) ---------------------------
#define XB0   0        // four 16KB fp16 X tiles (128x64)
#define XB1   16384
#define XB2   32768
#define XB3   49152
#define SBOND 65536    // 512B: bond_emb fp16, uint4[32]
#define SDS   66048    // 512 f
#define SWD0  68096    // 512 f
#define SBD0  70144    // 128 f
#define SBIA  70656    // 64 f
#define SBLI  70912    // 64 f
#define SBD1  71168    // 64 f
#define SPV   71424    // 128 f
#define SPR   71936    // 128 i
#define SMEM_BYTES 72448

// ------------------------------ asm helpers --------------------------------
__device__ __forceinline__ void ldm_x4(uint32_t* r, uint32_t a) {
    asm volatile("ldmatrix.sync.aligned.m8n8.x4.shared.b16 {%0,%1,%2,%3}, [%4];"
                 : "=r"(r[0]), "=r"(r[1]), "=r"(r[2]), "=r"(r[3]) : "r"(a));
}
__device__ __forceinline__ void mma16816(float* d, const uint32_t* a, uint32_t b0, uint32_t b1) {
    asm volatile(
        "mma.sync.aligned.m16n8k16.row.col.f32.f16.f16.f32 "
        "{%0,%1,%2,%3}, {%4,%5,%6,%7}, {%8,%9}, {%0,%1,%2,%3};"
        : "+f"(d[0]), "+f"(d[1]), "+f"(d[2]), "+f"(d[3])
        : "r"(a[0]), "r"(a[1]), "r"(a[2]), "r"(a[3]), "r"(b0), "r"(b1));
}
__device__ __forceinline__ uint32_t s2u(const void* p) {
    uint32_t a;
    asm("{ .reg .u64 t; cvta.to.shared.u64 t, %1; cvt.u32.u64 %0, t; }" : "=r"(a) : "l"(p));
    return a;
}
__device__ __forceinline__ uint32_t pack_h2(float a, float b) {
    __half2 h = __floats2half2_rn(a, b);
    return *(uint32_t*)&h;
}
// vectorized no-return float2 reduction (sm_90+, base ISA feature)
__device__ __forceinline__ void red_add_v2(float* ptr, float a, float b) {
    asm volatile("red.global.add.v2.f32 [%0], {%1, %2};"
                 :: "l"(ptr), "f"(a), "f"(b) : "memory");
}

// ---- m32 x n(16*NFP) warp GEMM over K=64, single fp16 term ------------------
template<int NFP>
__device__ __forceinline__ void gemm_tile(float (&acc)[2][2 * NFP][4], uint32_t xh,
                                          const uint4* __restrict__ wf, int nfp0,
                                          int rbase, int lane) {
    const int sub = lane >> 3, rin = lane & 7;
    const uint32_t aRow = (uint32_t)(rbase + ((sub & 1) << 3) + rin) * 128;
    const uint32_t aCol = (uint32_t)((sub >> 1) << 4);
    #pragma unroll
    for (int kc = 0; kc < 4; kc++) {
        uint32_t aoff = SWZ(aRow + aCol + kc * 32);
        uint32_t ah0[4], ah1[4];
        ldm_x4(ah0, xh + aoff);
        ldm_x4(ah1, xh + aoff + 2048);   // +16 rows
        uint4 bfr[NFP];
        #pragma unroll
        for (int pg = 0; pg < NFP; pg++)
            bfr[pg] = wf[(kc * 4 + nfp0 + pg) * 32 + lane];
        #pragma unroll
        for (int pg = 0; pg < NFP; pg++) {
            mma16816(acc[0][2 * pg + 0], ah0, bfr[pg].x, bfr[pg].y);
            mma16816(acc[1][2 * pg + 0], ah1, bfr[pg].x, bfr[pg].y);
            mma16816(acc[0][2 * pg + 1], ah0, bfr[pg].z, bfr[pg].w);
            mma16816(acc[1][2 * pg + 1], ah1, bfr[pg].z, bfr[pg].w);
        }
    }
}

// ============================================================================
// prep: build fp16 B-fragment tables + fp16 nfeat table + zero the output
// (memset folded in: saves one full-grid launch and overlaps with convert)
// ============================================================================
__global__ void prep_kernel(const float* __restrict__ weights,
                            const float* __restrict__ w_lin,
                            const float* __restrict__ w_deg1,
                            const float* __restrict__ nfeat,
                            float* __restrict__ out, int out_size) {
    int idx = blockIdx.x * 256 + threadIdx.x;
    // zero out[]: strided float4 stores across the whole grid
    {
        int n4 = out_size >> 2;              // number of float4 elements
        int stride = gridDim.x * 256;
        for (int j = idx; j < n4; j += stride)
            ((float4*)out)[j] = make_float4(0.f, 0.f, 0.f, 0.f);
    }
    if (idx < 8192) {
        const int lane = idx & 31;
        const int nfp  = (idx >> 5) & 3;
        const int kc   = (idx >> 7) & 3;
        const int ce = nfp * 16 + (lane >> 2);
        const int co = ce + 8;
        const int kb = kc * 16 + (lane & 3) * 2;
        {
            int a = idx >> 9;
            uint4 v;
            v.x = pack_h2(weights[(((kb + 0) << 6) + ce) * 16 + a],
                          weights[(((kb + 1) << 6) + ce) * 16 + a]);
            v.y = pack_h2(weights[(((kb + 8) << 6) + ce) * 16 + a],
                          weights[(((kb + 9) << 6) + ce) * 16 + a]);
            v.z = pack_h2(weights[(((kb + 0) << 6) + co) * 16 + a],
                          weights[(((kb + 1) << 6) + co) * 16 + a]);
            v.w = pack_h2(weights[(((kb + 8) << 6) + co) * 16 + a],
                          weights[(((kb + 9) << 6) + co) * 16 + a]);
            g_W1f[idx] = v;
        }
        if (idx < 512) {
            const float* se = w_lin + ce * 64;
            const float* so = w_lin + co * 64;
            uint4 v;
            v.x = pack_h2(se[kb], se[kb + 1]);
            v.y = pack_h2(se[kb + 8], se[kb + 9]);
            v.z = pack_h2(so[kb], so[kb + 1]);
            v.w = pack_h2(so[kb + 8], so[kb + 9]);
            g_W2f[idx] = v;
        }
        if (idx < 1024) {
            int ch = idx >> 9;
            const float* se = w_deg1 + ce * 128 + ch * 64;
            const float* so = w_deg1 + co * 128 + ch * 64;
            uint4 v;
            v.x = pack_h2(se[kb], se[kb + 1]);
            v.y = pack_h2(se[kb + 8], se[kb + 9]);
            v.z = pack_h2(so[kb], so[kb + 1]);
            v.w = pack_h2(so[kb + 8], so[kb + 9]);
            g_W3f[idx] = v;
        }
    } else {
        int j = idx - 8192;                 // 0 .. N_NODES*8-1
        if (j < N_NODES * 8) {
            const float4* src = (const float4*)(nfeat) + (size_t)j * 2;
            float4 a = src[0], b = src[1];
            uint4 v;
            v.x = pack_h2(a.x, a.y); v.y = pack_h2(a.z, a.w);
            v.z = pack_h2(b.x, b.y); v.w = pack_h2(b.z, b.w);
            g_nfh[j] = v;
        }
    }
}

// ============================================================================
// fused: warp-specialized, fp16, decoupled named-barrier pipeline (4 buffers)
// ============================================================================
__global__ __launch_bounds__(256, 2)
void fused_kernel(const float* __restrict__ degs,
                  const float* __restrict__ n2p_val,
                  const float* __restrict__ e2p_val,
                  const float* __restrict__ pool_val,
                  const float* __restrict__ bias,
                  const float* __restrict__ w_deg0,
                  const float* __restrict__ b_deg0,
                  const float* __restrict__ b_deg1,
                  const float* __restrict__ b_lin,
                  const float* __restrict__ bond_emb,
                  const int*   __restrict__ edge_feat_idx,
                  const int*   __restrict__ n2p_col,
                  const int*   __restrict__ e2p_col,
                  const int*   __restrict__ pool_row,
                  float*       __restrict__ out) {
    extern __shared__ char sm[];
    const uint32_t SB = s2u(sm);
    const int tid = threadIdx.x;
    const int warp = tid >> 5, lane = tid & 31;
    const int p0 = blockIdx.x * PT;

    uint4* s_bondh = (uint4*)(sm + SBOND);
    float* s_ds   = (float*)(sm + SDS);
    float* s_wd0  = (float*)(sm + SWD0);
    float* s_bd0  = (float*)(sm + SBD0);
    float* s_bia  = (float*)(sm + SBIA);
    float* s_bli  = (float*)(sm + SBLI);
    float* s_bd1  = (float*)(sm + SBD1);
    float* s_pv   = (float*)(sm + SPV);
    int*   s_pr   = (int*)(sm + SPR);

    if (tid < 32) {   // bond_emb -> fp16, 4 rows x 8 uint4
        int row = tid >> 3, c8 = tid & 7;
        const float* s = bond_emb + row * 64 + c8 * 8;
        uint4 v;
        v.x = pack_h2(s[0], s[1]); v.y = pack_h2(s[2], s[3]);
        v.z = pack_h2(s[4], s[5]); v.w = pack_h2(s[6], s[7]);
        s_bondh[tid] = v;
    }
    for (int i = tid; i < 512; i += 256) s_wd0[i] = w_deg0[i];
    if (tid < 128) s_bd0[tid] = b_deg0[tid];
    if (tid < 64) { s_bia[tid] = bias[tid]; s_bli[tid] = b_lin[tid]; s_bd1[tid] = b_deg1[tid]; }
    __syncthreads();

    const int rbase = (warp & 3) * 32;

    float acc1[2][8][4];
    #pragma unroll
    for (int m = 0; m < 2; m++)
        #pragma unroll
        for (int n = 0; n < 8; n++)
            #pragma unroll
            for (int j = 0; j < 4; j++) acc1[m][n][j] = 0.f;

    const int p = tid - 128;                 // producer row id (warp>=4)
    const bool valid = (p0 + p) < P_PERM;
    const int pc = valid ? (p0 + p) : (P_PERM - 1);

    int ncs[4], bjs[4];
    float vns[4], ves[4];

    // ======== mainloop: 8 epochs x 2 slices, decoupled named barriers ========
    // pair b (buffers 2b,2b+1) filled at epoch e (b=e&1), consumed at e+1.
    #pragma unroll
    for (int e = 0; e < 8; e++) {
        if (warp >= 4) {
            const int b = e & 1;
            if (b == 0) {                    // load 4-slice index group + prefetch bj
                int g = e >> 1;
                int4 nc4 = ((const int4*)n2p_col)[pc * 4 + g];
                int4 ec4 = ((const int4*)e2p_col)[pc * 4 + g];
                float4 vn4 = ((const float4*)n2p_val)[pc * 4 + g];
                float4 ve4 = ((const float4*)e2p_val)[pc * 4 + g];
                ncs[0] = nc4.x; ncs[1] = nc4.y; ncs[2] = nc4.z; ncs[3] = nc4.w;
                vns[0] = vn4.x; vns[1] = vn4.y; vns[2] = vn4.z; vns[3] = vn4.w;
                ves[0] = ve4.x; ves[1] = ve4.y; ves[2] = ve4.z; ves[3] = ve4.w;
                bjs[0] = edge_feat_idx[ec4.x];   // 4 independent dependent-loads,
                bjs[1] = edge_feat_idx[ec4.y];   // overlapped here instead of
                bjs[2] = edge_feat_idx[ec4.z];   // serializing one per slice
                bjs[3] = edge_feat_idx[ec4.w];
            }
            if (e >= 2) BAR_SYNC(BAR_FREE0 + b);   // wait pair free
            #pragma unroll
            for (int s = 0; s < 2; s++) {
                const int a = 2 * e + s;
                const int ai = a & 3;
                int nc = ncs[ai];
                int bj = bjs[ai];
                float vn = valid ? vns[ai] : 0.f;
                float ve = valid ? ves[ai] : 0.f;
                if (ai == (a >> 2)) s_ds[p * 4 + (a >> 2)] = vn * degs[nc]; // a%5==0
                char* xh = sm + (2 * b + s) * 16384;
                const int r0 = (warp - 4) * 32;
                #pragma unroll
                for (int pass = 0; pass < 8; pass++) {
                    int src = pass * 4 + (lane >> 3);
                    int   nc_r = __shfl_sync(FULLM, nc, src);
                    int   bj_r = __shfl_sync(FULLM, bj, src);
                    float vn_r = __shfl_sync(FULLM, vn, src);
                    float ve_r = __shfl_sync(FULLM, ve, src);
                    int row = r0 + pass * 4 + (lane >> 3);
                    uint4 nv = g_nfh[(size_t)nc_r * 8 + (lane & 7)];     // 1 LDG.128
                    uint4 bv = s_bondh[bj_r * 8 + (lane & 7)];           // 1 LDS.128
                    __half2 vn2 = __float2half2_rn(vn_r);
                    __half2 ve2 = __float2half2_rn(ve_r);
                    uint4 v;
                    *(__half2*)&v.x = __hfma2(vn2, *(const __half2*)&nv.x,
                                              __hmul2(ve2, *(const __half2*)&bv.x));
                    *(__half2*)&v.y = __hfma2(vn2, *(const __half2*)&nv.y,
                                              __hmul2(ve2, *(const __half2*)&bv.y));
                    *(__half2*)&v.z = __hfma2(vn2, *(const __half2*)&nv.z,
                                              __hmul2(ve2, *(const __half2*)&bv.z));
                    *(__half2*)&v.w = __hfma2(vn2, *(const __half2*)&nv.w,
                                              __hmul2(ve2, *(const __half2*)&bv.w));
                    uint32_t off = SWZ((uint32_t)row * 128 + ((lane & 7) << 4));
                    *(uint4*)(xh + off) = v;
                }
            }
            BAR_ARRIVE(BAR_FULL0 + b);             // pair filled
        } else if (e > 0) {
            const int b = (e - 1) & 1;
            BAR_SYNC(BAR_FULL0 + b);               // wait pair full
            #pragma unroll
            for (int s = 0; s < 2; s++) {
                const int a = 2 * (e - 1) + s;
                gemm_tile<4>(acc1, SB + (2 * b + s) * 16384, g_W1f + a * 512, 0, rbase, lane);
            }
            BAR_ARRIVE(BAR_FREE0 + b);             // pair free
        }
    }

    // ===================== epilogue phase A ==================================
    // consumers: sync FULL1, gemm slices 14 (XB2), 15 (XB3); relu(acc1+bias)->XB0 (own rows)
    // producers: sync FREE0, t0 -> XB1, pool staging
    if (warp < 4) {
        BAR_SYNC(BAR_FULL1);
        gemm_tile<4>(acc1, SB + XB2, g_W1f + 14 * 512, 0, rbase, lane);
        gemm_tile<4>(acc1, SB + XB3, g_W1f + 15 * 512, 0, rbase, lane);
        #pragma unroll
        for (int mt = 0; mt < 2; mt++)
            #pragma unroll
            for (int nf = 0; nf < 8; nf++) {
                int c0 = nf * 8 + (lane & 3) * 2;
                #pragma unroll
                for (int pr2 = 0; pr2 < 2; pr2++) {
                    int row = rbase + mt * 16 + (lane >> 2) + pr2 * 8;
                    float f0 = fmaxf(acc1[mt][nf][pr2 * 2 + 0] + s_bia[c0], 0.f);
                    float f1 = fmaxf(acc1[mt][nf][pr2 * 2 + 1] + s_bia[c0 + 1], 0.f);
                    uint32_t off = SWZ((uint32_t)row * 128 + (uint32_t)c0 * 2);
                    *(uint32_t*)(sm + XB0 + off) = pack_h2(f0, f1);
                }
            }
    } else {
        BAR_SYNC(BAR_FREE0);
        float4 dv = *(const float4*)&s_ds[p * 4];
        #pragma unroll
        for (int g = 0; g < 8; g++) {
            float f[8];
            #pragma unroll
            for (int j = 0; j < 8; j++) {
                int k = g * 8 + j;
                float4 w = *(const float4*)&s_wd0[k * 4];
                f[j] = fmaxf(dv.x * w.x + dv.y * w.y + dv.z * w.z + dv.w * w.w + s_bd0[k], 0.f);
            }
            uint4 v;
            v.x = pack_h2(f[0], f[1]); v.y = pack_h2(f[2], f[3]);
            v.z = pack_h2(f[4], f[5]); v.w = pack_h2(f[6], f[7]);
            uint32_t off = SWZ((uint32_t)p * 128 + g * 16);
            *(uint4*)(sm + XB1 + off) = v;
        }
        s_pv[p] = valid ? pool_val[p0 + p] : 0.f;
        s_pr[p] = valid ? pool_row[p0 + p] : 0;
    }
    __syncthreads();

    // ===================== epilogue phase B ==================================
    // consumers: acc2 = relu(h) @ W2^T (reads XB0 own rows); producers: t1 -> XB2
    float acc2[2][8][4];
    if (warp < 4) {
        #pragma unroll
        for (int m = 0; m < 2; m++)
            #pragma unroll
            for (int n = 0; n < 8; n++)
                #pragma unroll
                for (int j = 0; j < 4; j++) acc2[m][n][j] = 0.f;
        gemm_tile<4>(acc2, SB + XB0, g_W2f, 0, rbase, lane);
    } else {
        float4 dv = *(const float4*)&s_ds[p * 4];
        #pragma unroll
        for (int g = 0; g < 8; g++) {
            float f[8];
            #pragma unroll
            for (int j = 0; j < 8; j++) {
                int k = 64 + g * 8 + j;
                float4 w = *(const float4*)&s_wd0[k * 4];
                f[j] = fmaxf(dv.x * w.x + dv.y * w.y + dv.z * w.z + dv.w * w.w + s_bd0[k], 0.f);
            }
            uint4 v;
            v.x = pack_h2(f[0], f[1]); v.y = pack_h2(f[2], f[3]);
            v.z = pack_h2(f[4], f[5]); v.w = pack_h2(f[6], f[7]);
            uint32_t off = SWZ((uint32_t)p * 128 + g * 16);
            *(uint4*)(sm + XB2 + off) = v;
        }
    }
    __syncthreads();

    // ===================== epilogue phase C: gate, combine, scatter ==========
    if (warp < 4) {
        #pragma unroll
        for (int half = 0; half < 2; half++) {
            float acc3[2][4][4];
            #pragma unroll
            for (int m = 0; m < 2; m++)
                #pragma unroll
                for (int n = 0; n < 4; n++)
                    #pragma unroll
                    for (int j = 0; j < 4; j++) acc3[m][n][j] = 0.f;
            gemm_tile<2>(acc3, SB + XB1, g_W3f, half * 2, rbase, lane);        // t0 x W3 chunk0
            gemm_tile<2>(acc3, SB + XB2, g_W3f + 512, half * 2, rbase, lane);  // t1 x W3 chunk1
            #pragma unroll
            for (int mt = 0; mt < 2; mt++)
                #pragma unroll
                for (int fn = 0; fn < 4; fn++) {
                    int nf = half * 4 + fn;
                    int c0 = nf * 8 + (lane & 3) * 2;
                    #pragma unroll
                    for (int pr2 = 0; pr2 < 2; pr2++) {
                        int row = rbase + mt * 16 + (lane >> 2) + pr2 * 8;
                        if (p0 + row < P_PERM) {
                            float pv = s_pv[row];
                            int pr = s_pr[row];
                            float h2a = acc2[mt][nf][pr2 * 2 + 0] + s_bli[c0];
                            float h2b = acc2[mt][nf][pr2 * 2 + 1] + s_bli[c0 + 1];
                            float ga  = acc3[mt][fn][pr2 * 2 + 0] + s_bd1[c0];
                            float gb  = acc3[mt][fn][pr2 * 2 + 1] + s_bd1[c0 + 1];
                            red_add_v2(&out[((size_t)pr << 6) + c0],
                                       pv * h2a * ga, pv * h2b * gb);
                        }
                    }
                }
        }
    }
}

// ============================================================================
extern "C" void kernel_launch(void* const* d_in, const int* in_sizes, int n_in,
                              void* d_out, int out_size) {
    const float* nfeat         = (const float*)d_in[0];
    const float* degs          = (const float*)d_in[1];
    const float* n2p_val       = (const float*)d_in[2];
    const float* e2p_val       = (const float*)d_in[3];
    const float* pool_val      = (const float*)d_in[4];
    const float* weights       = (const float*)d_in[5];
    const float* bias          = (const float*)d_in[6];
    const float* w_deg0        = (const float*)d_in[7];
    const float* b_deg0        = (const float*)d_in[8];
    const float* w_deg1        = (const float*)d_in[9];
    const float* b_deg1        = (const float*)d_in[10];
    const float* w_lin         = (const float*)d_in[11];
    const float* b_lin         = (const float*)d_in[12];
    const float* bond_emb      = (const float*)d_in[13];
    const int*   edge_feat_idx = (const int*)d_in[14];
    const int*   n2p_col       = (const int*)d_in[16];
    const int*   e2p_col       = (const int*)d_in[18];
    const int*   pool_row      = (const int*)d_in[19];
    float* out = (float*)d_out;

    // memset folded into prep_kernel (zeroes out[] with strided float4 stores)
    prep_kernel<<<(8192 + N_NODES * 8 + 255) / 256, 256>>>(weights, w_lin, w_deg1,
                                                           nfeat, out, out_size);

    cudaFuncSetAttribute(fused_kernel, cudaFuncAttributeMaxDynamicSharedMemorySize, SMEM_BYTES);
    fused_kernel<<<NTILES, 256, SMEM_BYTES>>>(degs, n2p_val, e2p_val, pool_val,
                                              bias, w_deg0, b_deg0, b_deg1, b_lin,
                                              bond_emb, edge_feat_idx, n2p_col, e2p_col,
                                              pool_row, out);
}